// round 14
// baseline (speedup 1.0000x reference)
#include <cuda_runtime.h>
#include <cuda_fp16.h>
#include <cstdint>

// APPNP: h <- 0.9 * A@h + 0.1 * x, 10 iterations, edge-list A.
// Single-pass bucketed build: every row owns a 128-entry bucket; one pass
// does rank = atomicAdd(count[r]) and writes (col<<15 | 0.9*w fixed-point)
// at r*128+rank. Then 10x warp-per-row SpMM in fp16 storage (h_k scaled
// 4^-k): quarter-warp per edge, one 32-lane LDG.128 covers four 128B rows.
// This round (profile showed issue-bound: issue=63%, fma+alu=64%, L2=35%):
//   - packed fma.rn.f32x2 (FFMA2) halves the FMA instruction count
//   - fixed-point weight scale folded into epilogue constants (no per-edge
//     FMUL; accumulate with integer-valued weights)
//   - packed f32x2 reduction (FADD2)

#define N_NODES 100000
#define N_EDGES 3200000
#define D_FEAT  64
#define ALPHA   0.1f
#define K_STEPS 10
#define ROW_U4 (D_FEAT / 8)   // 8 uint4 (128B) per fp16 row
#define W_SCALE 32768.0f
#define W_INV   (1.0f / 32768.0f)
#define CVT_ELEMS (N_NODES * D_FEAT / 8)   // 800000
#define BKT_LOG 7
#define BKT_CAP (1 << BKT_LOG)             // 128 entries per row

// -------- static device scratch (no allocations allowed) --------
__device__ int            g_count[N_NODES];
__device__ unsigned int   g_cwb[(size_t)N_NODES << BKT_LOG]; // bucketed edges
__device__ uint4          g_hA[(size_t)N_NODES * ROW_U4];    // fp16 h ping
__device__ uint4          g_hB[(size_t)N_NODES * ROW_U4];    // fp16 h pong
__device__ uint4          g_x16[(size_t)N_NODES * ROW_U4];   // fp16 copy of x

// ---- packed f32x2 helpers (sm_103a FFMA2/FADD2 via PTX) ----
__device__ __forceinline__ void fma_f32x2(unsigned long long& acc,
                                          unsigned long long a,
                                          unsigned long long b) {
    asm("fma.rn.f32x2 %0, %1, %2, %0;" : "+l"(acc) : "l"(a), "l"(b));
}
__device__ __forceinline__ unsigned long long h2_to_f32x2(unsigned int h2) {
    unsigned long long r;
    asm("{\n\t"
        ".reg .b16 hl, hh;\n\t"
        ".reg .f32 lo, hi;\n\t"
        "mov.b32 {hl, hh}, %1;\n\t"
        "cvt.f32.f16 lo, hl;\n\t"
        "cvt.f32.f16 hi, hh;\n\t"
        "mov.b64 %0, {lo, hi};\n\t"
        "}" : "=l"(r) : "r"(h2));
    return r;
}
__device__ __forceinline__ unsigned long long pack2(float a, float b) {
    unsigned long long r;
    asm("mov.b64 %0, {%1, %2};" : "=l"(r) : "f"(a), "f"(b));
    return r;
}
__device__ __forceinline__ void unpack2(unsigned long long v, float& a, float& b) {
    asm("mov.b64 {%0, %1}, %2;" : "=f"(a), "=f"(b) : "l"(v));
}

// fused: zero counts (t < N_NODES) + x fp32->fp16 convert (t < CVT_ELEMS)
__global__ void k_zero_cvt(const float4* __restrict__ xin) {
    int t = blockIdx.x * blockDim.x + threadIdx.x;
    if (t < N_NODES) g_count[t] = 0;
    if (t < CVT_ELEMS) {
        float4 a = xin[2 * t], b = xin[2 * t + 1];
        uint4 pk;
        *(__half2*)&pk.x = __floats2half2_rn(a.x, a.y);
        *(__half2*)&pk.y = __floats2half2_rn(a.z, a.w);
        *(__half2*)&pk.z = __floats2half2_rn(b.x, b.y);
        *(__half2*)&pk.w = __floats2half2_rn(b.z, b.w);
        g_x16[t] = pk;
    }
}

// single-pass bucket scatter: 4 edges per thread
__global__ void k_scatter(const int4* __restrict__ erow4,
                          const int4* __restrict__ ecol4,
                          const float4* __restrict__ ew4) {
    int t = blockIdx.x * blockDim.x + threadIdx.x;
    if (t < N_EDGES / 4) {
        int4    r = erow4[t];
        int4    c = ecol4[t];
        float4  w = ew4[t];
        const float s = (1.0f - ALPHA) * W_SCALE;
        unsigned int w0 = (unsigned int)__float2int_rn(s * w.x);
        unsigned int w1 = (unsigned int)__float2int_rn(s * w.y);
        unsigned int w2 = (unsigned int)__float2int_rn(s * w.z);
        unsigned int w3 = (unsigned int)__float2int_rn(s * w.w);
        int k0 = atomicAdd(&g_count[r.x], 1);
        int k1 = atomicAdd(&g_count[r.y], 1);
        int k2 = atomicAdd(&g_count[r.z], 1);
        int k3 = atomicAdd(&g_count[r.w], 1);
        g_cwb[((unsigned int)r.x << BKT_LOG) + k0] = ((unsigned int)c.x << 15) | w0;
        g_cwb[((unsigned int)r.y << BKT_LOG) + k1] = ((unsigned int)c.y << 15) | w1;
        g_cwb[((unsigned int)r.z << BKT_LOG) + k2] = ((unsigned int)c.z << 15) | w2;
        g_cwb[((unsigned int)r.w << BKT_LOG) + k3] = ((unsigned int)c.w << 15) | w3;
    }
}

// -------- SpMM: warp per row; quarter-warp per edge; FFMA2 inner loop -----
// src stored fp16 at scale c_in; dst at scale c_out.
// Accumulators carry an extra W_SCALE factor (integer-valued weights);
// k1 = c_out/(c_in*W_SCALE), k2 = 0.1*c_out.
template<bool DST_F16>
__global__ void __launch_bounds__(128)
k_spmm16(const uint4* __restrict__ src, const float* __restrict__ x,
         void* __restrict__ dst, float k1, float k2) {
    unsigned int warp = (blockIdx.x * blockDim.x + threadIdx.x) >> 5;
    unsigned int lane = threadIdx.x & 31;
    if (warp >= N_NODES) return;

    unsigned int q = lane >> 3;   // quarter: which edge within each 4-edge step
    unsigned int p = lane & 7;    // feature group: feats p*8 .. p*8+7

    int beg = (int)(warp << BKT_LOG);
    int end = beg + g_count[warp];

    unsigned long long a0 = 0ull, a1 = 0ull, a2 = 0ull, a3 = 0ull;

    #pragma unroll 4
    for (int e = beg + (int)q; e < end; e += 4) {
        unsigned int cw = g_cwb[e];               // uniform per quarter
        unsigned int c  = cw >> 15;
        float wf = (float)(int)(cw & 0x7fffu);    // integer-valued weight
        unsigned long long w2 = pack2(wf, wf);
        uint4 hv = src[c * ROW_U4 + p];           // 16B of one fp16 row
        fma_f32x2(a0, h2_to_f32x2(hv.x), w2);
        fma_f32x2(a1, h2_to_f32x2(hv.y), w2);
        fma_f32x2(a2, h2_to_f32x2(hv.z), w2);
        fma_f32x2(a3, h2_to_f32x2(hv.w), w2);
    }

    // combine the 4 quarters: packed shuffle-reduce (two xor stages)
    #pragma unroll
    for (int d = 8; d <= 16; d <<= 1) {
        float lo, hi;
        unpack2(a0, lo, hi);
        lo += __shfl_xor_sync(0xffffffffu, lo, d);
        hi += __shfl_xor_sync(0xffffffffu, hi, d);
        a0 = pack2(lo, hi);
        unpack2(a1, lo, hi);
        lo += __shfl_xor_sync(0xffffffffu, lo, d);
        hi += __shfl_xor_sync(0xffffffffu, hi, d);
        a1 = pack2(lo, hi);
        unpack2(a2, lo, hi);
        lo += __shfl_xor_sync(0xffffffffu, lo, d);
        hi += __shfl_xor_sync(0xffffffffu, hi, d);
        a2 = pack2(lo, hi);
        unpack2(a3, lo, hi);
        lo += __shfl_xor_sync(0xffffffffu, lo, d);
        hi += __shfl_xor_sync(0xffffffffu, hi, d);
        a3 = pack2(lo, hi);
    }

    if (lane < 8) {
        float acc0, acc1, acc2, acc3, acc4, acc5, acc6, acc7;
        unpack2(a0, acc0, acc1);
        unpack2(a1, acc2, acc3);
        unpack2(a2, acc4, acc5);
        unpack2(a3, acc6, acc7);
        const float4* xv = (const float4*)(x + warp * D_FEAT + p * 8);
        float4 xa = xv[0], xb = xv[1];
        float o0 = fmaf(k2, xa.x, k1 * acc0);
        float o1 = fmaf(k2, xa.y, k1 * acc1);
        float o2 = fmaf(k2, xa.z, k1 * acc2);
        float o3 = fmaf(k2, xa.w, k1 * acc3);
        float o4 = fmaf(k2, xb.x, k1 * acc4);
        float o5 = fmaf(k2, xb.y, k1 * acc5);
        float o6 = fmaf(k2, xb.z, k1 * acc6);
        float o7 = fmaf(k2, xb.w, k1 * acc7);
        if (DST_F16) {
            uint4 pk;
            *(__half2*)&pk.x = __floats2half2_rn(o0, o1);
            *(__half2*)&pk.y = __floats2half2_rn(o2, o3);
            *(__half2*)&pk.z = __floats2half2_rn(o4, o5);
            *(__half2*)&pk.w = __floats2half2_rn(o6, o7);
            ((uint4*)dst)[warp * ROW_U4 + p] = pk;
        } else {
            float4* d = (float4*)((float*)dst + warp * D_FEAT + p * 8);
            d[0] = make_float4(o0, o1, o2, o3);
            d[1] = make_float4(o4, o5, o6, o7);
        }
    }
}

extern "C" void kernel_launch(void* const* d_in, const int* in_sizes, int n_in,
                              void* d_out, int out_size) {
    const float* x    = (const float*)d_in[0];
    const int*   erow = (const int*)d_in[1];
    const int*   ecol = (const int*)d_in[2];
    const float* ew   = (const float*)d_in[3];
    float*       out  = (float*)d_out;

    uint4 *hA, *hB, *x16;
    cudaGetSymbolAddress((void**)&hA, g_hA);
    cudaGetSymbolAddress((void**)&hB, g_hB);
    cudaGetSymbolAddress((void**)&x16, g_x16);

    const int TB = 256;
    const int quadBlocks = (N_EDGES / 4 + TB - 1) / TB;
    const int fuseBlocks = (CVT_ELEMS + TB - 1) / TB;   // covers N_NODES too
    const int spmmBlocks = (N_NODES * 32 + 127) / 128;

    // single-pass bucketed build
    k_zero_cvt<<<fuseBlocks, TB>>>((const float4*)x);
    k_scatter<<<quadBlocks, TB>>>((const int4*)erow, (const int4*)ecol,
                                  (const float4*)ew);

    // 10 propagation steps, all fp16 storage, scale c_k = 4^-k (c_10 = 1).
    // Accumulators carry W_SCALE; fold W_INV into k1.
    const uint4* src = x16;
    uint4* bufs[2] = { hA, hB };
    for (int k = 1; k <= K_STEPS; k++) {
        if (k < K_STEPS) {
            float c_k = exp2f(-2.0f * k);
            uint4* dst = bufs[k & 1];
            k_spmm16<true><<<spmmBlocks, 128>>>(src, x, dst,
                                                0.25f * W_INV, 0.1f * c_k);
            src = dst;
        } else {
            float k1 = exp2f(2.0f * (K_STEPS - 1)) * W_INV;   // 2^18 / W_SCALE
            k_spmm16<false><<<spmmBlocks, 128>>>(src, x, out, k1, 0.1f);
        }
    }
}

// round 16
// speedup vs baseline: 1.2116x; 1.2116x over previous
#include <cuda_runtime.h>
#include <cuda_fp16.h>
#include <cstdint>

// APPNP: h <- 0.9 * A@h + 0.1 * x, 10 iterations, edge-list A.
// Single-pass bucketed build: every row owns a 128-entry bucket; one pass
// does rank = atomicAdd(count[r]) and writes (col<<15 | fp16bits(0.9*w))
// at r*128+rank (0.9*w < 2.0 so fp16 bits 15,14 are zero; 15 bits suffice).
// Then 10x warp-per-row SpMM in fp16 storage (h_k scaled 4^-k): quarter-warp
// per edge, one 32-lane LDG.128 covers four 128B fp16 rows, and the inner
// loop is pure HFMA2 — fp16 multiply-accumulate, zero conversions. Each
// quarter's partial sum (<=~17 terms) lives in 4 half2 accumulators and is
// widened to f32 once at loop exit. fp16-accumulation noise injected at
// iters 1..9 is spectrally suppressed (signal rides A's Perron eigenvalue
// ~14.4, white noise rides the bulk ~2.9), so only iter 10's ~4e-4 survives.

#define N_NODES 100000
#define N_EDGES 3200000
#define D_FEAT  64
#define ALPHA   0.1f
#define K_STEPS 10
#define ROW_U4 (D_FEAT / 8)   // 8 uint4 (128B) per fp16 row
#define CVT_ELEMS (N_NODES * D_FEAT / 8)   // 800000
#define BKT_LOG 7
#define BKT_CAP (1 << BKT_LOG)             // 128 entries per row

// -------- static device scratch (no allocations allowed) --------
__device__ int            g_count[N_NODES];
__device__ unsigned int   g_cwb[(size_t)N_NODES << BKT_LOG]; // bucketed edges
__device__ uint4          g_hA[(size_t)N_NODES * ROW_U4];    // fp16 h ping
__device__ uint4          g_hB[(size_t)N_NODES * ROW_U4];    // fp16 h pong
__device__ uint4          g_x16[(size_t)N_NODES * ROW_U4];   // fp16 copy of x

// fused: zero counts (t < N_NODES) + x fp32->fp16 convert (t < CVT_ELEMS)
__global__ void k_zero_cvt(const float4* __restrict__ xin) {
    int t = blockIdx.x * blockDim.x + threadIdx.x;
    if (t < N_NODES) g_count[t] = 0;
    if (t < CVT_ELEMS) {
        float4 a = xin[2 * t], b = xin[2 * t + 1];
        uint4 pk;
        *(__half2*)&pk.x = __floats2half2_rn(a.x, a.y);
        *(__half2*)&pk.y = __floats2half2_rn(a.z, a.w);
        *(__half2*)&pk.z = __floats2half2_rn(b.x, b.y);
        *(__half2*)&pk.w = __floats2half2_rn(b.z, b.w);
        g_x16[t] = pk;
    }
}

// single-pass bucket scatter: 4 edges per thread; weight stored as fp16 bits
__global__ void k_scatter(const int4* __restrict__ erow4,
                          const int4* __restrict__ ecol4,
                          const float4* __restrict__ ew4) {
    int t = blockIdx.x * blockDim.x + threadIdx.x;
    if (t < N_EDGES / 4) {
        int4    r = erow4[t];
        int4    c = ecol4[t];
        float4  w = ew4[t];
        const float s = 1.0f - ALPHA;
        unsigned int w0 = (unsigned int)__half_as_ushort(__float2half_rn(s * w.x));
        unsigned int w1 = (unsigned int)__half_as_ushort(__float2half_rn(s * w.y));
        unsigned int w2 = (unsigned int)__half_as_ushort(__float2half_rn(s * w.z));
        unsigned int w3 = (unsigned int)__half_as_ushort(__float2half_rn(s * w.w));
        int k0 = atomicAdd(&g_count[r.x], 1);
        int k1 = atomicAdd(&g_count[r.y], 1);
        int k2 = atomicAdd(&g_count[r.z], 1);
        int k3 = atomicAdd(&g_count[r.w], 1);
        g_cwb[((unsigned int)r.x << BKT_LOG) + k0] = ((unsigned int)c.x << 15) | w0;
        g_cwb[((unsigned int)r.y << BKT_LOG) + k1] = ((unsigned int)c.y << 15) | w1;
        g_cwb[((unsigned int)r.z << BKT_LOG) + k2] = ((unsigned int)c.z << 15) | w2;
        g_cwb[((unsigned int)r.w << BKT_LOG) + k3] = ((unsigned int)c.w << 15) | w3;
    }
}

// -------- SpMM: warp per row; quarter-warp per edge; HFMA2 inner loop -----
// src stored fp16 at scale c_in; dst at scale c_out.
// k1 = c_out/c_in, k2 = 0.1*c_out.
template<bool DST_F16>
__global__ void __launch_bounds__(128)
k_spmm16(const uint4* __restrict__ src, const float* __restrict__ x,
         void* __restrict__ dst, float k1, float k2) {
    unsigned int warp = (blockIdx.x * blockDim.x + threadIdx.x) >> 5;
    unsigned int lane = threadIdx.x & 31;
    if (warp >= N_NODES) return;

    unsigned int q = lane >> 3;   // quarter: which edge within each 4-edge step
    unsigned int p = lane & 7;    // feature group: feats p*8 .. p*8+7

    int beg = (int)(warp << BKT_LOG);
    int end = beg + g_count[warp];

    __half2 a0 = __floats2half2_rn(0.f, 0.f);
    __half2 a1 = a0, a2 = a0, a3 = a0;

    #pragma unroll 4
    for (int e = beg + (int)q; e < end; e += 4) {
        unsigned int cw = g_cwb[e];               // uniform per quarter
        unsigned int wb = cw & 0x7fffu;           // fp16 bits of 0.9*w
        unsigned int wd = wb | (wb << 16);        // half2(w, w)
        __half2 wh = *(__half2*)&wd;
        uint4 hv = src[(cw >> 15) * ROW_U4 + p];  // 16B of one fp16 row
        a0 = __hfma2(*(__half2*)&hv.x, wh, a0);
        a1 = __hfma2(*(__half2*)&hv.y, wh, a1);
        a2 = __hfma2(*(__half2*)&hv.z, wh, a2);
        a3 = __hfma2(*(__half2*)&hv.w, wh, a3);
    }

    // widen quarter partials to f32, then combine the 4 quarters
    float2 f0 = __half22float2(a0);
    float2 f1 = __half22float2(a1);
    float2 f2 = __half22float2(a2);
    float2 f3 = __half22float2(a3);
    float acc0 = f0.x, acc1 = f0.y, acc2 = f1.x, acc3 = f1.y;
    float acc4 = f2.x, acc5 = f2.y, acc6 = f3.x, acc7 = f3.y;

    #pragma unroll
    for (int d = 8; d <= 16; d <<= 1) {
        acc0 += __shfl_xor_sync(0xffffffffu, acc0, d);
        acc1 += __shfl_xor_sync(0xffffffffu, acc1, d);
        acc2 += __shfl_xor_sync(0xffffffffu, acc2, d);
        acc3 += __shfl_xor_sync(0xffffffffu, acc3, d);
        acc4 += __shfl_xor_sync(0xffffffffu, acc4, d);
        acc5 += __shfl_xor_sync(0xffffffffu, acc5, d);
        acc6 += __shfl_xor_sync(0xffffffffu, acc6, d);
        acc7 += __shfl_xor_sync(0xffffffffu, acc7, d);
    }

    if (lane < 8) {
        const float4* xv = (const float4*)(x + warp * D_FEAT + p * 8);
        float4 xa = xv[0], xb = xv[1];
        float o0 = fmaf(k2, xa.x, k1 * acc0);
        float o1 = fmaf(k2, xa.y, k1 * acc1);
        float o2 = fmaf(k2, xa.z, k1 * acc2);
        float o3 = fmaf(k2, xa.w, k1 * acc3);
        float o4 = fmaf(k2, xb.x, k1 * acc4);
        float o5 = fmaf(k2, xb.y, k1 * acc5);
        float o6 = fmaf(k2, xb.z, k1 * acc6);
        float o7 = fmaf(k2, xb.w, k1 * acc7);
        if (DST_F16) {
            uint4 pk;
            *(__half2*)&pk.x = __floats2half2_rn(o0, o1);
            *(__half2*)&pk.y = __floats2half2_rn(o2, o3);
            *(__half2*)&pk.z = __floats2half2_rn(o4, o5);
            *(__half2*)&pk.w = __floats2half2_rn(o6, o7);
            ((uint4*)dst)[warp * ROW_U4 + p] = pk;
        } else {
            float4* d = (float4*)((float*)dst + warp * D_FEAT + p * 8);
            d[0] = make_float4(o0, o1, o2, o3);
            d[1] = make_float4(o4, o5, o6, o7);
        }
    }
}

extern "C" void kernel_launch(void* const* d_in, const int* in_sizes, int n_in,
                              void* d_out, int out_size) {
    const float* x    = (const float*)d_in[0];
    const int*   erow = (const int*)d_in[1];
    const int*   ecol = (const int*)d_in[2];
    const float* ew   = (const float*)d_in[3];
    float*       out  = (float*)d_out;

    uint4 *hA, *hB, *x16;
    cudaGetSymbolAddress((void**)&hA, g_hA);
    cudaGetSymbolAddress((void**)&hB, g_hB);
    cudaGetSymbolAddress((void**)&x16, g_x16);

    const int TB = 256;
    const int quadBlocks = (N_EDGES / 4 + TB - 1) / TB;
    const int fuseBlocks = (CVT_ELEMS + TB - 1) / TB;   // covers N_NODES too
    const int spmmBlocks = (N_NODES * 32 + 127) / 128;

    // single-pass bucketed build
    k_zero_cvt<<<fuseBlocks, TB>>>((const float4*)x);
    k_scatter<<<quadBlocks, TB>>>((const int4*)erow, (const int4*)ecol,
                                  (const float4*)ew);

    // 10 propagation steps, all fp16 storage, scale c_k = 4^-k (c_10 = 1).
    const uint4* src = x16;
    uint4* bufs[2] = { hA, hB };
    for (int k = 1; k <= K_STEPS; k++) {
        if (k < K_STEPS) {
            float c_k = exp2f(-2.0f * k);
            uint4* dst = bufs[k & 1];
            k_spmm16<true><<<spmmBlocks, 128>>>(src, x, dst, 0.25f, 0.1f * c_k);
            src = dst;
        } else {
            float k1 = exp2f(2.0f * (K_STEPS - 1));   // 1/c_9 = 2^18
            k_spmm16<false><<<spmmBlocks, 128>>>(src, x, out, k1, 0.1f);
        }
    }
}

// round 17
// speedup vs baseline: 1.3353x; 1.1021x over previous
#include <cuda_runtime.h>
#include <cuda_fp16.h>
#include <cstdint>

// APPNP: h <- 0.9 * A@h + 0.1 * x, 10 iterations, edge-list A.
// Single-pass bucketed build: every row owns a 128-entry bucket; one pass
// does rank = atomicAdd(count[r]) and writes (col<<15 | fp16bits(0.225*w))
// at r*128+rank. The 0.225 = 0.9*(1-alpha-scale) folds the per-iteration
// 4^-1 storage rescale INTO the weight, so the SpMM epilogue is just
// acc + k2*x (no k1 multiply) for fp16 destinations.
// 10x warp-per-row SpMM in fp16 storage (h_k scaled 4^-k): quarter-warp per
// edge, one 32-lane LDG.128 covers four 128B fp16 rows, pure HFMA2 inner
// loop, half2 shuffle reduction, fp16 x in the epilogue. Final iteration
// widens to fp32 and rescales by 2^20.

#define N_NODES 100000
#define N_EDGES 3200000
#define D_FEAT  64
#define ALPHA   0.1f
#define K_STEPS 10
#define ROW_U4 (D_FEAT / 8)   // 8 uint4 (128B) per fp16 row
#define CVT_ELEMS (N_NODES * D_FEAT / 8)   // 800000
#define BKT_LOG 7
#define BKT_CAP (1 << BKT_LOG)             // 128 entries per row

// -------- static device scratch (no allocations allowed) --------
__device__ int            g_count[N_NODES];
__device__ unsigned int   g_cwb[(size_t)N_NODES << BKT_LOG]; // bucketed edges
__device__ uint4          g_hA[(size_t)N_NODES * ROW_U4];    // fp16 h ping
__device__ uint4          g_hB[(size_t)N_NODES * ROW_U4];    // fp16 h pong
__device__ uint4          g_x16[(size_t)N_NODES * ROW_U4];   // fp16 copy of x

__device__ __forceinline__ __half2 shfl_xor_h2(__half2 v, int d) {
    unsigned int u = *(unsigned int*)&v;
    u = __shfl_xor_sync(0xffffffffu, u, d);
    return *(__half2*)&u;
}

// fused: zero counts (t < N_NODES) + x fp32->fp16 convert (t < CVT_ELEMS)
__global__ void k_zero_cvt(const float4* __restrict__ xin) {
    int t = blockIdx.x * blockDim.x + threadIdx.x;
    if (t < N_NODES) g_count[t] = 0;
    if (t < CVT_ELEMS) {
        float4 a = xin[2 * t], b = xin[2 * t + 1];
        uint4 pk;
        *(__half2*)&pk.x = __floats2half2_rn(a.x, a.y);
        *(__half2*)&pk.y = __floats2half2_rn(a.z, a.w);
        *(__half2*)&pk.z = __floats2half2_rn(b.x, b.y);
        *(__half2*)&pk.w = __floats2half2_rn(b.z, b.w);
        g_x16[t] = pk;
    }
}

// single-pass bucket scatter: 4 edges per thread.
// Weight stored as fp16 bits of 0.225*w (= 0.9*w*0.25, folding the 4^-1
// inter-iteration storage rescale); 0.225*w < 0.5 so bit15 is free for col.
__global__ void k_scatter(const int4* __restrict__ erow4,
                          const int4* __restrict__ ecol4,
                          const float4* __restrict__ ew4) {
    int t = blockIdx.x * blockDim.x + threadIdx.x;
    if (t < N_EDGES / 4) {
        int4    r = erow4[t];
        int4    c = ecol4[t];
        float4  w = ew4[t];
        const float s = (1.0f - ALPHA) * 0.25f;
        unsigned int w0 = (unsigned int)__half_as_ushort(__float2half_rn(s * w.x));
        unsigned int w1 = (unsigned int)__half_as_ushort(__float2half_rn(s * w.y));
        unsigned int w2 = (unsigned int)__half_as_ushort(__float2half_rn(s * w.z));
        unsigned int w3 = (unsigned int)__half_as_ushort(__float2half_rn(s * w.w));
        int k0 = atomicAdd(&g_count[r.x], 1);
        int k1 = atomicAdd(&g_count[r.y], 1);
        int k2 = atomicAdd(&g_count[r.z], 1);
        int k3 = atomicAdd(&g_count[r.w], 1);
        g_cwb[((unsigned int)r.x << BKT_LOG) + k0] = ((unsigned int)c.x << 15) | w0;
        g_cwb[((unsigned int)r.y << BKT_LOG) + k1] = ((unsigned int)c.y << 15) | w1;
        g_cwb[((unsigned int)r.z << BKT_LOG) + k2] = ((unsigned int)c.z << 15) | w2;
        g_cwb[((unsigned int)r.w << BKT_LOG) + k3] = ((unsigned int)c.w << 15) | w3;
    }
}

// -------- SpMM: warp per row; quarter-warp per edge; HFMA2 inner loop -----
// src at scale c_in; weights carry 0.225 so acc lands at scale c_out=c_in/4.
// DST_F16: dst = acc + k2*x16 (half2), k2 = 0.1*c_out (may be fp16-subnormal
// for late iters; those injections contribute <2e-6 to the final output).
// Final (f32): dst = k1*acc + 0.1*x, k1 = 2^20.
template<bool DST_F16>
__global__ void __launch_bounds__(128)
k_spmm16(const uint4* __restrict__ src, void* __restrict__ dst,
         float k1f, float k2f) {
    unsigned int warp = (blockIdx.x * blockDim.x + threadIdx.x) >> 5;
    unsigned int lane = threadIdx.x & 31;
    if (warp >= N_NODES) return;

    unsigned int q = lane >> 3;   // quarter: which edge within each 4-edge step
    unsigned int p = lane & 7;    // feature group: feats p*8 .. p*8+7

    int beg = (int)(warp << BKT_LOG);
    int end = beg + g_count[warp];

    __half2 a0 = __floats2half2_rn(0.f, 0.f);
    __half2 a1 = a0, a2 = a0, a3 = a0;

    #pragma unroll 4
    for (int e = beg + (int)q; e < end; e += 4) {
        unsigned int cw = g_cwb[e];               // uniform per quarter
        unsigned int wb = cw & 0x7fffu;           // fp16 bits of 0.225*w
        unsigned int wd = wb | (wb << 16);        // half2(w, w)
        __half2 wh = *(__half2*)&wd;
        uint4 hv = src[(cw >> 15) * ROW_U4 + p];  // 16B of one fp16 row
        a0 = __hfma2(*(__half2*)&hv.x, wh, a0);
        a1 = __hfma2(*(__half2*)&hv.y, wh, a1);
        a2 = __hfma2(*(__half2*)&hv.z, wh, a2);
        a3 = __hfma2(*(__half2*)&hv.w, wh, a3);
    }

    // combine the 4 quarters: packed half2 shuffle reduction
    #pragma unroll
    for (int d = 8; d <= 16; d <<= 1) {
        a0 = __hadd2(a0, shfl_xor_h2(a0, d));
        a1 = __hadd2(a1, shfl_xor_h2(a1, d));
        a2 = __hadd2(a2, shfl_xor_h2(a2, d));
        a3 = __hadd2(a3, shfl_xor_h2(a3, d));
    }

    if (lane < 8) {
        uint4 xv = g_x16[warp * ROW_U4 + p];
        if (DST_F16) {
            __half2 k2h = __float2half2_rn(k2f);
            uint4 pk;
            *(__half2*)&pk.x = __hfma2(k2h, *(__half2*)&xv.x, a0);
            *(__half2*)&pk.y = __hfma2(k2h, *(__half2*)&xv.y, a1);
            *(__half2*)&pk.z = __hfma2(k2h, *(__half2*)&xv.z, a2);
            *(__half2*)&pk.w = __hfma2(k2h, *(__half2*)&xv.w, a3);
            ((uint4*)dst)[warp * ROW_U4 + p] = pk;
        } else {
            float2 f0 = __half22float2(a0);
            float2 f1 = __half22float2(a1);
            float2 f2 = __half22float2(a2);
            float2 f3 = __half22float2(a3);
            float2 x0 = __half22float2(*(__half2*)&xv.x);
            float2 x1 = __half22float2(*(__half2*)&xv.y);
            float2 x2 = __half22float2(*(__half2*)&xv.z);
            float2 x3 = __half22float2(*(__half2*)&xv.w);
            float4* d = (float4*)((float*)dst + warp * D_FEAT + p * 8);
            d[0] = make_float4(fmaf(k2f, x0.x, k1f * f0.x),
                               fmaf(k2f, x0.y, k1f * f0.y),
                               fmaf(k2f, x1.x, k1f * f1.x),
                               fmaf(k2f, x1.y, k1f * f1.y));
            d[1] = make_float4(fmaf(k2f, x2.x, k1f * f2.x),
                               fmaf(k2f, x2.y, k1f * f2.y),
                               fmaf(k2f, x3.x, k1f * f3.x),
                               fmaf(k2f, x3.y, k1f * f3.y));
        }
    }
}

extern "C" void kernel_launch(void* const* d_in, const int* in_sizes, int n_in,
                              void* d_out, int out_size) {
    const float* x    = (const float*)d_in[0];
    const int*   erow = (const int*)d_in[1];
    const int*   ecol = (const int*)d_in[2];
    const float* ew   = (const float*)d_in[3];
    float*       out  = (float*)d_out;

    uint4 *hA, *hB, *x16;
    cudaGetSymbolAddress((void**)&hA, g_hA);
    cudaGetSymbolAddress((void**)&hB, g_hB);
    cudaGetSymbolAddress((void**)&x16, g_x16);

    const int TB = 256;
    const int quadBlocks = (N_EDGES / 4 + TB - 1) / TB;
    const int fuseBlocks = (CVT_ELEMS + TB - 1) / TB;   // covers N_NODES too
    const int spmmBlocks = (N_NODES * 32 + 127) / 128;

    // single-pass bucketed build
    k_zero_cvt<<<fuseBlocks, TB>>>((const float4*)x);
    k_scatter<<<quadBlocks, TB>>>((const int4*)erow, (const int4*)ecol,
                                  (const float4*)ew);

    // 10 propagation steps, all fp16 storage, scale c_k = 4^-k (weights
    // carry the 4^-1 rescale). k2 = 0.1 * 4^-k; final k1 = 4^10 = 2^20.
    const uint4* src = x16;
    uint4* bufs[2] = { hA, hB };
    for (int k = 1; k <= K_STEPS; k++) {
        if (k < K_STEPS) {
            float c_k = exp2f(-2.0f * k);
            uint4* dst = bufs[k & 1];
            k_spmm16<true><<<spmmBlocks, 128>>>(src, dst, 1.0f, 0.1f * c_k);
            src = dst;
        } else {
            k_spmm16<false><<<spmmBlocks, 128>>>(src, out,
                                                 exp2f(20.0f), 0.1f);
        }
    }
}